// round 2
// baseline (speedup 1.0000x reference)
#include <cuda_runtime.h>
#include <cstdint>

// ---------------------------------------------------------------------------
// Problem constants
// ---------------------------------------------------------------------------
#define B_   2
#define N_   65536      // unknown points
#define M_   16384      // known points
#define C1_  128        // unknow_feats channels
#define C2_  256        // known_feats channels
#define H1_  256        // mlp hidden
#define H2_  128        // mlp out
#define NT1_ 512        // N-tile count for n=65536 / 128
#define EPS_ 1e-5f

// ---------------------------------------------------------------------------
// Scratch (device globals -- no allocation allowed)
// ---------------------------------------------------------------------------
__device__ __align__(16) float4 g_kpack[B_ * M_];                 // (x,y,z,|k|^2)
__device__ int    g_idx[B_ * N_];                                 // 1-NN index
__device__ float  g_P[(size_t)B_ * H1_ * M_];                     // w1a @ known_feats
__device__ float  g_h[(size_t)B_ * H1_ * N_];                     // pre-BN hidden
__device__ float  g_part1[(size_t)B_ * H1_ * NT1_ * 2];           // layer1 stats partials
__device__ float  g_part2[(size_t)B_ * H2_ * NT1_ * 2];           // layer2 stats partials
__device__ float  g_scale1[H1_], g_bias1[H1_];
__device__ float  g_scale2[H2_], g_bias2[H2_];

// ---------------------------------------------------------------------------
// K0: pack known points as float4 (x, y, z, k2) where
// k2 = (x*x + y*y) + z*z with explicit fp32 rounding per op (XLA reduce order).
// ---------------------------------------------------------------------------
__global__ void prep_kernel(const float* __restrict__ known) {
    int j = blockIdx.x * 256 + threadIdx.x;
    if (j < B_ * M_) {
        float kx = known[3 * j + 0];
        float ky = known[3 * j + 1];
        float kz = known[3 * j + 2];
        float k2 = __fadd_rn(__fadd_rn(__fmul_rn(kx, kx), __fmul_rn(ky, ky)),
                             __fmul_rn(kz, kz));
        g_kpack[j] = make_float4(kx, ky, kz, k2);
    }
}

// ---------------------------------------------------------------------------
// K1: brute-force 1-NN replicating the reference arithmetic EXACTLY:
//   dot = fmaf(uz,kz, fmaf(uy,ky, ux*kx))      (cuBLAS K-ascending fma chain)
//   d   = (u2 - 2*dot) + k2                    (left-to-right elementwise)
//   first-min under strict <, ascending k      (== chunked min/argmin scan)
// grid(128, B), 128 threads, 4 unknowns/thread; known streamed via smem.
// ---------------------------------------------------------------------------
#define NN_CHUNK 2048
__global__ void __launch_bounds__(128) nn_kernel(const float* __restrict__ unknown) {
    __shared__ __align__(16) float4 sk[NN_CHUNK];
    const int b  = blockIdx.y;
    const int i0 = blockIdx.x * 512;
    const int t  = threadIdx.x;

    float ux[4], uy[4], uz[4], u2[4], bd[4];
    int   bi[4];
#pragma unroll
    for (int u = 0; u < 4; u++) {
        int i = i0 + t + u * 128;
        const float* up = unknown + ((size_t)b * N_ + i) * 3;
        ux[u] = up[0]; uy[u] = up[1]; uz[u] = up[2];
        u2[u] = __fadd_rn(__fadd_rn(__fmul_rn(ux[u], ux[u]), __fmul_rn(uy[u], uy[u])),
                          __fmul_rn(uz[u], uz[u]));
        bd[u] = 3.4e38f; bi[u] = 0;
    }

    const float4* gk = g_kpack + (size_t)b * M_;
    for (int c0 = 0; c0 < M_; c0 += NN_CHUNK) {
        __syncthreads();
#pragma unroll
        for (int j = 0; j < NN_CHUNK / 128; j++)
            sk[t + j * 128] = gk[c0 + t + j * 128];
        __syncthreads();

#pragma unroll 4
        for (int k = 0; k < NN_CHUNK; k++) {
            float4 kp = sk[k];
#pragma unroll
            for (int u = 0; u < 4; u++) {
                // cuBLAS-style fma chain, K ascending (x, y, z)
                float dot = __fmul_rn(ux[u], kp.x);
                dot = fmaf(uy[u], kp.y, dot);
                dot = fmaf(uz[u], kp.z, dot);
                // (u2 - 2*dot) + k2, each op rounded fp32, no contraction
                float d = __fadd_rn(__fsub_rn(u2[u], __fmul_rn(2.0f, dot)), kp.w);
                if (d < bd[u]) { bd[u] = d; bi[u] = c0 + k; }
            }
        }
    }
#pragma unroll
    for (int u = 0; u < 4; u++)
        g_idx[(size_t)b * N_ + i0 + t + u * 128] = bi[u];
}

// ---------------------------------------------------------------------------
// Generic fused SIMT GEMM:  Y[b,o,i] = sum_c W[o, woff+c] * X[b,c,i]
//   optional: + P[b,o,idx[b,i]]     (GATHER)
//   optional: X transformed as relu(x*bsc[c]+bbi[c]) at load    (BN)
//   optional: per-CTA deterministic (sum, sumsq) partials       (STATS)
// Tile 128x128, BK=16, 256 threads, 8x8 microtile.
// ---------------------------------------------------------------------------
template <int KDIM, bool GATHER, bool BN, bool STATS, int MTOT>
__global__ void __launch_bounds__(256) gemm_kernel(
    const float* __restrict__ W, int ldw, int woff,
    const float* __restrict__ X, int N,
    const float* __restrict__ P,
    const int*   __restrict__ idx,
    const float* __restrict__ bsc,
    const float* __restrict__ bbi,
    float* __restrict__ Y,
    float* __restrict__ part)
{
    __shared__ __align__(16) float Ws[16][132];
    __shared__ __align__(16) float Xs[16][132];

    const int b   = blockIdx.z;
    const int ob0 = blockIdx.y * 128;
    const int ib0 = blockIdx.x * 128;
    const int t   = threadIdx.x;
    const int tr  = t & 15;      // i-direction microtile
    const int tc  = t >> 4;      // o-direction microtile

    const float* Wp = W + woff;
    const float* Xb = X + (size_t)b * KDIM * N;

    float acc[8][8];
#pragma unroll
    for (int j = 0; j < 8; j++)
#pragma unroll
        for (int i = 0; i < 8; i++) acc[j][i] = 0.f;

    for (int k0 = 0; k0 < KDIM; k0 += 16) {
        // load W tile (128 rows x 16 cols) transposed into Ws[c][r]
        {
            int c = t & 15, r0 = t >> 4;
#pragma unroll
            for (int j = 0; j < 8; j++) {
                int r = r0 + j * 16;
                Ws[c][r] = Wp[(size_t)(ob0 + r) * ldw + k0 + c];
            }
        }
        // load X tile (16 rows x 128 cols), optional BN+ReLU transform
        {
            int ic = (t & 31) * 4, kr0 = t >> 5;
#pragma unroll
            for (int j = 0; j < 2; j++) {
                int kr = kr0 + j * 8;
                int c  = k0 + kr;
                float4 v = *(const float4*)(Xb + (size_t)c * N + ib0 + ic);
                if (BN) {
                    float s = bsc[c], bb = bbi[c];
                    v.x = fmaxf(fmaf(v.x, s, bb), 0.f);
                    v.y = fmaxf(fmaf(v.y, s, bb), 0.f);
                    v.z = fmaxf(fmaf(v.z, s, bb), 0.f);
                    v.w = fmaxf(fmaf(v.w, s, bb), 0.f);
                }
                *(float4*)(&Xs[kr][ic]) = v;
            }
        }
        __syncthreads();
#pragma unroll
        for (int kk = 0; kk < 16; kk++) {
            float a[8], x[8];
            *(float4*)(a)     = *(const float4*)(&Ws[kk][tc * 8]);
            *(float4*)(a + 4) = *(const float4*)(&Ws[kk][tc * 8 + 4]);
            *(float4*)(x)     = *(const float4*)(&Xs[kk][tr * 8]);
            *(float4*)(x + 4) = *(const float4*)(&Xs[kk][tr * 8 + 4]);
#pragma unroll
            for (int j = 0; j < 8; j++)
#pragma unroll
                for (int i = 0; i < 8; i++)
                    acc[j][i] = fmaf(a[j], x[i], acc[j][i]);
        }
        __syncthreads();
    }

    if (GATHER) {
        int id[8];
#pragma unroll
        for (int i = 0; i < 8; i++)
            id[i] = idx[(size_t)b * N + ib0 + tr * 8 + i];
#pragma unroll
        for (int j = 0; j < 8; j++) {
            const float* Pr = P + ((size_t)b * MTOT + ob0 + tc * 8 + j) * M_;
#pragma unroll
            for (int i = 0; i < 8; i++)
                acc[j][i] += __ldg(&Pr[id[i]]);
        }
    }

    // write output
#pragma unroll
    for (int j = 0; j < 8; j++) {
        float* Yr = Y + ((size_t)b * MTOT + ob0 + tc * 8 + j) * N + ib0 + tr * 8;
        *(float4*)(Yr)     = *(float4*)(&acc[j][0]);
        *(float4*)(Yr + 4) = *(float4*)(&acc[j][4]);
    }

    if (STATS) {
        float* sred = &Ws[0][0];   // reuse smem (needs 2048 floats, have 2112)
        float s1[8], s2[8];
#pragma unroll
        for (int j = 0; j < 8; j++) {
            float a = 0.f, q = 0.f;
#pragma unroll
            for (int i = 0; i < 8; i++) {
                a += acc[j][i];
                q = fmaf(acc[j][i], acc[j][i], q);
            }
            s1[j] = a; s2[j] = q;
        }
        __syncthreads();
#pragma unroll
        for (int j = 0; j < 8; j++) sred[(tc * 8 + j) * 16 + tr] = s1[j];
        __syncthreads();
        if (t < 128) {
            float tot = 0.f;
#pragma unroll
            for (int r = 0; r < 16; r++) tot += sred[t * 16 + r];
            part[(((size_t)b * MTOT + ob0 + t) * gridDim.x + blockIdx.x) * 2 + 0] = tot;
        }
        __syncthreads();
#pragma unroll
        for (int j = 0; j < 8; j++) sred[(tc * 8 + j) * 16 + tr] = s2[j];
        __syncthreads();
        if (t < 128) {
            float tot = 0.f;
#pragma unroll
            for (int r = 0; r < 16; r++) tot += sred[t * 16 + r];
            part[(((size_t)b * MTOT + ob0 + t) * gridDim.x + blockIdx.x) * 2 + 1] = tot;
        }
    }
}

// ---------------------------------------------------------------------------
// Finalize BN stats -> per-channel (scale, bias) for fused apply
// ---------------------------------------------------------------------------
template <int MTOT>
__global__ void fin_kernel(const float* __restrict__ part, int NT,
                           const float* __restrict__ gamma,
                           const float* __restrict__ beta,
                           float* __restrict__ sc, float* __restrict__ bi,
                           float invN)
{
    int o = threadIdx.x;
    if (o >= MTOT) return;
    float s1 = 0.f, s2 = 0.f;
    for (int b = 0; b < B_; b++)
        for (int q = 0; q < NT; q++) {
            const float* p = part + (((size_t)b * MTOT + o) * NT + q) * 2;
            s1 += p[0];
            s2 += p[1];
        }
    float mean = s1 * invN;
    float var  = s2 * invN - mean * mean;
    float rstd = rsqrtf(var + EPS_);
    float s    = gamma[o] * rstd;
    sc[o] = s;
    bi[o] = beta[o] - mean * s;
}

// ---------------------------------------------------------------------------
// Final elementwise BN+ReLU in-place on d_out
// ---------------------------------------------------------------------------
__global__ void bnfin_kernel(float* __restrict__ Y,
                             const float* __restrict__ sc,
                             const float* __restrict__ bi)
{
    int row = blockIdx.y;            // 0 .. B_*H2_-1
    int ch  = row & (H2_ - 1);
    size_t base = (size_t)row * N_;
    int i = (blockIdx.x * 256 + threadIdx.x) * 4;
    float4 v = *(float4*)(Y + base + i);
    float s = sc[ch], b = bi[ch];
    v.x = fmaxf(fmaf(v.x, s, b), 0.f);
    v.y = fmaxf(fmaf(v.y, s, b), 0.f);
    v.z = fmaxf(fmaf(v.z, s, b), 0.f);
    v.w = fmaxf(fmaf(v.w, s, b), 0.f);
    *(float4*)(Y + base + i) = v;
}

// ---------------------------------------------------------------------------
// Launch
// ---------------------------------------------------------------------------
extern "C" void kernel_launch(void* const* d_in, const int* in_sizes, int n_in,
                              void* d_out, int out_size)
{
    const float* unknown = (const float*)d_in[0];
    const float* known   = (const float*)d_in[1];
    const float* uf      = (const float*)d_in[2];   // (B, 128, n)
    const float* kf      = (const float*)d_in[3];   // (B, 256, m)
    const float* w1      = (const float*)d_in[4];   // (256, 384)
    const float* gamma1  = (const float*)d_in[5];
    const float* beta1   = (const float*)d_in[6];
    const float* w2      = (const float*)d_in[7];   // (128, 256)
    const float* gamma2  = (const float*)d_in[8];
    const float* beta2   = (const float*)d_in[9];
    float* out = (float*)d_out;

    float *pP, *ph, *pp1, *pp2, *ps1, *pb1, *ps2, *pb2;
    int* pidx;
    cudaGetSymbolAddress((void**)&pP,   g_P);
    cudaGetSymbolAddress((void**)&ph,   g_h);
    cudaGetSymbolAddress((void**)&pp1,  g_part1);
    cudaGetSymbolAddress((void**)&pp2,  g_part2);
    cudaGetSymbolAddress((void**)&ps1,  g_scale1);
    cudaGetSymbolAddress((void**)&pb1,  g_bias1);
    cudaGetSymbolAddress((void**)&ps2,  g_scale2);
    cudaGetSymbolAddress((void**)&pb2,  g_bias2);
    cudaGetSymbolAddress((void**)&pidx, g_idx);

    const float invN = 1.0f / (float)(B_ * N_);

    // K0: pack known points
    prep_kernel<<<(B_ * M_ + 255) / 256, 256>>>(known);

    // K1: 1-NN search
    nn_kernel<<<dim3(N_ / 512, B_), 128>>>(unknown);

    // K2: P = w1[:, :256] @ known_feats   (B, 256, m)
    gemm_kernel<C2_, false, false, false, H1_>
        <<<dim3(M_ / 128, H1_ / 128, B_), 256>>>(
            w1, 384, 0, kf, M_, nullptr, nullptr, nullptr, nullptr, pP, nullptr);

    // K3: h = w1[:, 256:] @ unknow_feats + gather(P, idx); stats1
    gemm_kernel<C1_, true, false, true, H1_>
        <<<dim3(N_ / 128, H1_ / 128, B_), 256>>>(
            w1, 384, C2_, uf, N_, pP, pidx, nullptr, nullptr, ph, pp1);

    // K4: finalize BN1 -> scale1/bias1
    fin_kernel<H1_><<<1, 256>>>(pp1, NT1_, gamma1, beta1, ps1, pb1, invN);

    // K5: out_pre = w2 @ relu(bn1(h)); stats2
    gemm_kernel<H1_, false, true, true, H2_>
        <<<dim3(N_ / 128, H2_ / 128, B_), 256>>>(
            w2, 256, 0, ph, N_, nullptr, nullptr, ps1, pb1, out, pp2);

    // K6: finalize BN2 -> scale2/bias2
    fin_kernel<H2_><<<1, 256>>>(pp2, NT1_, gamma2, beta2, ps2, pb2, invN);

    // K7: out = relu(bn2(out_pre)) in place
    bnfin_kernel<<<dim3(N_ / 1024, B_ * H2_), 256>>>(out, ps2, pb2);
}